// round 13
// baseline (speedup 1.0000x reference)
#include <cuda_runtime.h>
#include <cuda_fp16.h>
#include <cstdint>
#include <cstring>

// Problem constants (fixed by the dataset)
#define BB 2
#define SS 2048
#define HH 2048
#define HD 128
#define NH 16
#define MM (BB*SS)   // 4096

// ---------------- scratch (static device globals — no allocation) ----------
__device__ __half g_hh[(size_t)MM*HH];      // hidden hi
__device__ __half g_hl[(size_t)MM*HH];      // hidden lo
__device__ __half g_wq16[(size_t)HH*HH];    // weights fp16
__device__ __half g_wk16[(size_t)HD*HH];
__device__ __half g_wv16[(size_t)HD*HH];
__device__ __half g_wo16[(size_t)HH*HH];
__device__ __half g_qh[(size_t)MM*HH];      // Q hi/lo
__device__ __half g_ql[(size_t)MM*HH];
__device__ __half g_k [(size_t)MM*HD];      // K, V plain fp16
__device__ __half g_v [(size_t)MM*HD];
__device__ __half g_oh[(size_t)MM*HH];      // attention out hi/lo
__device__ __half g_ol[(size_t)MM*HH];
__device__ float  g_maskb[(size_t)BB*SS];

// ---------------- helpers ---------------------------------------------------
__device__ __forceinline__ uint32_t smem_u32(const void* p) {
    uint32_t a;
    asm("{ .reg .u64 t; cvta.to.shared.u64 t, %1; cvt.u32.u64 %0, t; }"
        : "=r"(a) : "l"(p));
    return a;
}

#define MMA_F16(d, a0, a1, a2, a3, b0, b1) asm volatile( \
    "mma.sync.aligned.m16n8k16.row.col.f32.f16.f16.f32 " \
    "{%0,%1,%2,%3}, {%4,%5,%6,%7}, {%8,%9}, {%0,%1,%2,%3};" \
    : "+f"((d)[0]), "+f"((d)[1]), "+f"((d)[2]), "+f"((d)[3]) \
    : "r"(a0), "r"(a1), "r"(a2), "r"(a3), "r"(b0), "r"(b1))

#define LDSM_X4(r0, r1, r2, r3, addr) asm volatile( \
    "ldmatrix.sync.aligned.m8n8.x4.shared.b16 {%0,%1,%2,%3}, [%4];" \
    : "=r"(r0), "=r"(r1), "=r"(r2), "=r"(r3) : "r"(addr))

#define LDSM_X4_T(r0, r1, r2, r3, addr) asm volatile( \
    "ldmatrix.sync.aligned.m8n8.x4.trans.shared.b16 {%0,%1,%2,%3}, [%4];" \
    : "=r"(r0), "=r"(r1), "=r"(r2), "=r"(r3) : "r"(addr))

#define CP_ASYNC16(s, g) asm volatile( \
    "cp.async.ca.shared.global [%0], [%1], 16;" :: "r"(s), "l"(g))
#define CP_ASYNC4(s, g) asm volatile( \
    "cp.async.ca.shared.global [%0], [%1], 4;" :: "r"(s), "l"(g))
#define CP_COMMIT() asm volatile("cp.async.commit_group;")
#define CP_WAIT0() asm volatile("cp.async.wait_group 0;")
#define CP_WAIT1() asm volatile("cp.async.wait_group 1;")
#define CP_WAIT2() asm volatile("cp.async.wait_group 2;")

__device__ __forceinline__ uint32_t h2_as_u32(__half x, __half y) {
    __half2 t = __halves2half2(x, y);
    uint32_t u; memcpy(&u, &t, 4); return u;
}

// ---------------- prep kernels ----------------------------------------------
__global__ __launch_bounds__(256) void split_f32(
    const float* __restrict__ x, __half* __restrict__ hi,
    __half* __restrict__ lo, int n4)
{
    int i = blockIdx.x * 256 + threadIdx.x;
    if (i >= n4) return;
    float4 v = reinterpret_cast<const float4*>(x)[i];
    __half hx = __float2half_rn(v.x), hy = __float2half_rn(v.y);
    __half hz = __float2half_rn(v.z), hw = __float2half_rn(v.w);
    reinterpret_cast<uint2*>(hi)[i] =
        make_uint2(h2_as_u32(hx, hy), h2_as_u32(hz, hw));
    reinterpret_cast<uint2*>(lo)[i] = make_uint2(
        h2_as_u32(__float2half_rn(v.x - __half2float(hx)),
                  __float2half_rn(v.y - __half2float(hy))),
        h2_as_u32(__float2half_rn(v.z - __half2float(hz)),
                  __float2half_rn(v.w - __half2float(hw))));
}

__global__ __launch_bounds__(256) void to_f16(
    const float* __restrict__ x, __half* __restrict__ y, int n4)
{
    int i = blockIdx.x * 256 + threadIdx.x;
    if (i >= n4) return;
    float4 v = reinterpret_cast<const float4*>(x)[i];
    reinterpret_cast<uint2*>(y)[i] = make_uint2(
        h2_as_u32(__float2half_rn(v.x), __float2half_rn(v.y)),
        h2_as_u32(__float2half_rn(v.z), __float2half_rn(v.w)));
}

__global__ void prep_maskb(const int* __restrict__ mask, float* __restrict__ mb)
{
    int i = blockIdx.x * 256 + threadIdx.x;
    if (i < BB * SS) mb[i] = mask[i] ? 0.f : -1e30f;
}

// ---------------- pipelined fp16 NT GEMM (2-pass compensated) --------------
// C[m][n] = alpha * sum_k (Ah+Al)[m][k]*B[n][k] (+ bias[n])
// All inputs already fp16; mainloop = cp.async(3-stage) + ldmatrix + MMA.
#define RSTR 80
#define TILEB (128*RSTR)       // 10240
#define STAGEB (3*TILEB)       // 30720
#define GSMEM (3*STAGEB)       // 92160

__global__ __launch_bounds__(256)
void gemm16(const __half* __restrict__ Ah, const __half* __restrict__ Al,
            const __half* __restrict__ Bh, const float* __restrict__ bias,
            float* __restrict__ C, __half* __restrict__ Ch,
            __half* __restrict__ Cl,
            int K, long long lda, long long ldb, long long ldc, float alpha)
{
    extern __shared__ __align__(16) unsigned char smem[];
    const uint32_t sb = smem_u32(smem);

    const int tid  = threadIdx.x;
    const int lane = tid & 31;
    const int warp = tid >> 5;
    const int gid  = lane >> 2;
    const int tig  = lane & 3;
    const int wm   = (warp >> 2) * 64;
    const int wn   = (warp & 3) * 32;

    const int rowBase = blockIdx.y * 128;
    const int colBase = blockIdx.x * 128;

    float acc[4][4][4];
#pragma unroll
    for (int i = 0; i < 4; i++)
#pragma unroll
        for (int j = 0; j < 4; j++)
#pragma unroll
            for (int c = 0; c < 4; c++) acc[i][j][c] = 0.f;

    const uint32_t aoff = (uint32_t)((wm + (lane & 15)) * RSTR
                        + ((lane >> 4) & 1) * 16);
    const uint32_t boff = (uint32_t)((wn + ((lane >> 4) & 1) * 8
                        + (lane & 7)) * RSTR + ((lane >> 3) & 1) * 16);

    auto issue = [&](int c) {
        const uint32_t base = sb + (uint32_t)(c % 3) * STAGEB;
        const int kt = c << 5;
#pragma unroll
        for (int i = 0; i < 2; i++) {
            int idx = tid + i * 256;       // 0..511
            int row = idx >> 2;            // 0..127
            int c16 = idx & 3;             // 16B chunk
            uint32_t so = (uint32_t)(row * RSTR + c16 * 16);
            CP_ASYNC16(base + so,
                       Ah + (size_t)(rowBase + row) * lda + kt + c16 * 8);
            CP_ASYNC16(base + TILEB + so,
                       Al + (size_t)(rowBase + row) * lda + kt + c16 * 8);
            CP_ASYNC16(base + 2 * TILEB + so,
                       Bh + (size_t)(colBase + row) * ldb + kt + c16 * 8);
        }
        CP_COMMIT();
    };

    const int nchunks = K >> 5;
    issue(0);
    issue(1);
    for (int c = 0; c < nchunks; c++) {
        if (c + 2 < nchunks) { issue(c + 2); CP_WAIT2(); }
        else                 { CP_WAIT0(); }
        __syncthreads();

        const uint32_t base = sb + (uint32_t)(c % 3) * STAGEB;
#pragma unroll
        for (int ks = 0; ks < 2; ks++) {
            const uint32_t ko = ks * 32;
            uint32_t ah[4][4], al[4][4], bh[4][2];
#pragma unroll
            for (int mf = 0; mf < 4; mf++) {
                uint32_t a = base + aoff + mf * (16 * RSTR) + ko;
                LDSM_X4(ah[mf][0], ah[mf][1], ah[mf][2], ah[mf][3], a);
                LDSM_X4(al[mf][0], al[mf][1], al[mf][2], al[mf][3], a + TILEB);
            }
#pragma unroll
            for (int nfp = 0; nfp < 2; nfp++) {
                uint32_t b = base + 2 * TILEB + boff + nfp * (16 * RSTR) + ko;
                LDSM_X4(bh[2*nfp][0], bh[2*nfp][1], bh[2*nfp+1][0], bh[2*nfp+1][1], b);
            }
#pragma unroll
            for (int mf = 0; mf < 4; mf++)
#pragma unroll
                for (int nf = 0; nf < 4; nf++) {
                    MMA_F16(acc[mf][nf], ah[mf][0], ah[mf][1], ah[mf][2], ah[mf][3],
                            bh[nf][0], bh[nf][1]);
                    MMA_F16(acc[mf][nf], al[mf][0], al[mf][1], al[mf][2], al[mf][3],
                            bh[nf][0], bh[nf][1]);
                }
        }
        __syncthreads();
    }

#pragma unroll
    for (int mf = 0; mf < 4; mf++) {
        int r0 = rowBase + wm + mf * 16 + gid;
#pragma unroll
        for (int nf = 0; nf < 4; nf++) {
            int c0 = colBase + wn + nf * 8 + 2 * tig;
            float b0 = 0.f, b1 = 0.f;
            if (bias) { b0 = bias[c0]; b1 = bias[c0 + 1]; }
            float v00 = acc[mf][nf][0] * alpha + b0;
            float v01 = acc[mf][nf][1] * alpha + b1;
            float v10 = acc[mf][nf][2] * alpha + b0;
            float v11 = acc[mf][nf][3] * alpha + b1;
            if (Ch && Cl) {          // split fp16 hi/lo output (Q)
                __half h00 = __float2half_rn(v00), h01 = __float2half_rn(v01);
                __half h10 = __float2half_rn(v10), h11 = __float2half_rn(v11);
                *reinterpret_cast<uint32_t*>(&Ch[(size_t)r0 * ldc + c0]) =
                    h2_as_u32(h00, h01);
                *reinterpret_cast<uint32_t*>(&Ch[(size_t)(r0 + 8) * ldc + c0]) =
                    h2_as_u32(h10, h11);
                *reinterpret_cast<uint32_t*>(&Cl[(size_t)r0 * ldc + c0]) =
                    h2_as_u32(__float2half_rn(v00 - __half2float(h00)),
                              __float2half_rn(v01 - __half2float(h01)));
                *reinterpret_cast<uint32_t*>(&Cl[(size_t)(r0 + 8) * ldc + c0]) =
                    h2_as_u32(__float2half_rn(v10 - __half2float(h10)),
                              __float2half_rn(v11 - __half2float(h11)));
            } else if (Ch) {         // plain fp16 output (K/V)
                *reinterpret_cast<uint32_t*>(&Ch[(size_t)r0 * ldc + c0]) =
                    h2_as_u32(__float2half_rn(v00), __float2half_rn(v01));
                *reinterpret_cast<uint32_t*>(&Ch[(size_t)(r0 + 8) * ldc + c0]) =
                    h2_as_u32(__float2half_rn(v10), __float2half_rn(v11));
            } else {                 // fp32 output (final)
                *reinterpret_cast<float2*>(&C[(size_t)r0 * ldc + c0]) =
                    make_float2(v00, v01);
                *reinterpret_cast<float2*>(&C[(size_t)(r0 + 8) * ldc + c0]) =
                    make_float2(v10, v11);
            }
        }
    }
}

// ---------------- fused flash attention (HMMA, 2-pass fp16) ----------------
#define ATT_STR 272
#define ATT_Q_H 0
#define ATT_Q_L (128*ATT_STR)
#define ATT_STAGE0 (2*128*ATT_STR)
#define ST_K 0
#define ST_V (64*ATT_STR)
#define ST_MB (2*64*ATT_STR)
#define ATT_STAGE_SZ (2*64*ATT_STR + 256)
#define ATT_SMEM (ATT_STAGE0 + 2*ATT_STAGE_SZ)

__global__ __launch_bounds__(256)
void flash_attn(const __half* __restrict__ qh, const __half* __restrict__ ql,
                const __half* __restrict__ kk, const __half* __restrict__ vv,
                const float* __restrict__ maskb,
                __half* __restrict__ oh, __half* __restrict__ ol)
{
    extern __shared__ __align__(16) unsigned char sm[];
    const uint32_t sb = smem_u32(sm);
    const int tid  = threadIdx.x;
    const int lane = tid & 31;
    const int warp = tid >> 5;
    const int gid  = lane >> 2;
    const int tig  = lane & 3;
    const int qb = blockIdx.x, h = blockIdx.y, b = blockIdx.z;
    const int wm = warp * 16;

#pragma unroll
    for (int i = 0; i < 16; i++) {
        const __half* src = (i < 8) ? qh : ql;
        uint32_t abase = (i < 8) ? ATT_Q_H : ATT_Q_L;
        int row = (tid >> 4) + (i & 7) * 16;
        int c16 = tid & 15;
        CP_ASYNC16(sb + abase + row * ATT_STR + c16 * 16,
                   src + ((size_t)(b * SS + qb * 128 + row)) * HH + h * HD + c16 * 8);
    }
    CP_COMMIT();

    auto issue_kv = [&](int it, int stg) {
        uint32_t base = sb + ATT_STAGE0 + stg * ATT_STAGE_SZ;
        int kv0 = it * 64;
#pragma unroll
        for (int i = 0; i < 8; i++) {
            const __half* src = (i < 4) ? kk : vv;
            uint32_t aoff2 = (i < 4) ? ST_K : ST_V;
            int row = (tid >> 4) + (i & 3) * 16;
            int c16 = tid & 15;
            CP_ASYNC16(base + aoff2 + row * ATT_STR + c16 * 16,
                       src + ((size_t)(b * SS + kv0 + row)) * HD + c16 * 8);
        }
        if (tid < 64)
            CP_ASYNC4(base + ST_MB + tid * 4, maskb + b * SS + kv0 + tid);
        CP_COMMIT();
    };

    float oacc[16][4];
#pragma unroll
    for (int i = 0; i < 16; i++)
#pragma unroll
        for (int j = 0; j < 4; j++) oacc[i][j] = 0.f;
    float m0 = -1e30f, m1 = -1e30f, l0 = 0.f, l1 = 0.f;
    const float ascale = 0.08838834764831845f;

    issue_kv(0, 0);

    const uint32_t aoff = (uint32_t)((wm + (lane & 15)) * ATT_STR
                        + ((lane >> 4) & 1) * 16);
    const uint32_t boff = (uint32_t)((((lane >> 4) & 1) * 8 + (lane & 7)) * ATT_STR
                        + ((lane >> 3) & 1) * 16);
    const uint32_t toff0 = (uint32_t)((lane & 15) * ATT_STR
                         + ((lane >> 4) & 1) * 16);

    for (int it = 0; it < 32; it++) {
        const int stg = it & 1;
        if (it + 1 < 32) { issue_kv(it + 1, stg ^ 1); CP_WAIT1(); }
        else             { CP_WAIT0(); }
        __syncthreads();

        const uint32_t stbase = sb + ATT_STAGE0 + stg * ATT_STAGE_SZ;

        float sacc[8][4];
#pragma unroll
        for (int i = 0; i < 8; i++)
#pragma unroll
            for (int j = 0; j < 4; j++) sacc[i][j] = 0.f;

#pragma unroll
        for (int ks = 0; ks < 8; ks++) {
            const uint32_t ko = ks * 32;
            uint32_t ah[4], al[4];
            LDSM_X4(ah[0], ah[1], ah[2], ah[3], sb + ATT_Q_H + aoff + ko);
            LDSM_X4(al[0], al[1], al[2], al[3], sb + ATT_Q_L + aoff + ko);
#pragma unroll
            for (int np = 0; np < 4; np++) {
                uint32_t bh[4];
                uint32_t ba = stbase + np * (16 * ATT_STR) + boff + ko;
                LDSM_X4(bh[0], bh[1], bh[2], bh[3], ba + ST_K);
                MMA_F16(sacc[2*np],   ah[0], ah[1], ah[2], ah[3], bh[0], bh[1]);
                MMA_F16(sacc[2*np],   al[0], al[1], al[2], al[3], bh[0], bh[1]);
                MMA_F16(sacc[2*np+1], ah[0], ah[1], ah[2], ah[3], bh[2], bh[3]);
                MMA_F16(sacc[2*np+1], al[0], al[1], al[2], al[3], bh[2], bh[3]);
            }
        }

        const float* mbp = reinterpret_cast<const float*>(
            sm + (size_t)(ATT_STAGE0 + stg * ATT_STAGE_SZ + ST_MB));
        float tm0 = -1e30f, tm1 = -1e30f;
#pragma unroll
        for (int nf = 0; nf < 8; nf++) {
            float mb0 = mbp[nf * 8 + 2 * tig];
            float mb1 = mbp[nf * 8 + 2 * tig + 1];
            sacc[nf][0] = sacc[nf][0] * ascale + mb0;
            sacc[nf][1] = sacc[nf][1] * ascale + mb1;
            sacc[nf][2] = sacc[nf][2] * ascale + mb0;
            sacc[nf][3] = sacc[nf][3] * ascale + mb1;
            tm0 = fmaxf(tm0, fmaxf(sacc[nf][0], sacc[nf][1]));
            tm1 = fmaxf(tm1, fmaxf(sacc[nf][2], sacc[nf][3]));
        }
        tm0 = fmaxf(tm0, __shfl_xor_sync(~0u, tm0, 1));
        tm0 = fmaxf(tm0, __shfl_xor_sync(~0u, tm0, 2));
        tm1 = fmaxf(tm1, __shfl_xor_sync(~0u, tm1, 1));
        tm1 = fmaxf(tm1, __shfl_xor_sync(~0u, tm1, 2));
        float nm0 = fmaxf(m0, tm0), nm1 = fmaxf(m1, tm1);
        float cor0 = __expf(m0 - nm0), cor1 = __expf(m1 - nm1);
        float rs0 = 0.f, rs1 = 0.f;
#pragma unroll
        for (int nf = 0; nf < 8; nf++) {
            sacc[nf][0] = __expf(sacc[nf][0] - nm0);
            sacc[nf][1] = __expf(sacc[nf][1] - nm0);
            sacc[nf][2] = __expf(sacc[nf][2] - nm1);
            sacc[nf][3] = __expf(sacc[nf][3] - nm1);
            rs0 += sacc[nf][0] + sacc[nf][1];
            rs1 += sacc[nf][2] + sacc[nf][3];
        }
        rs0 += __shfl_xor_sync(~0u, rs0, 1);
        rs0 += __shfl_xor_sync(~0u, rs0, 2);
        rs1 += __shfl_xor_sync(~0u, rs1, 1);
        rs1 += __shfl_xor_sync(~0u, rs1, 2);
        l0 = l0 * cor0 + rs0;  m0 = nm0;
        l1 = l1 * cor1 + rs1;  m1 = nm1;
#pragma unroll
        for (int nf = 0; nf < 16; nf++) {
            oacc[nf][0] *= cor0; oacc[nf][1] *= cor0;
            oacc[nf][2] *= cor1; oacc[nf][3] *= cor1;
        }

#pragma unroll
        for (int kf = 0; kf < 4; kf++) {
            __half e0h = __float2half_rn(sacc[2*kf][0]);
            __half e1h = __float2half_rn(sacc[2*kf][1]);
            __half e2h = __float2half_rn(sacc[2*kf][2]);
            __half e3h = __float2half_rn(sacc[2*kf][3]);
            __half f0h = __float2half_rn(sacc[2*kf+1][0]);
            __half f1h = __float2half_rn(sacc[2*kf+1][1]);
            __half f2h = __float2half_rn(sacc[2*kf+1][2]);
            __half f3h = __float2half_rn(sacc[2*kf+1][3]);
            uint32_t pa0 = h2_as_u32(e0h, e1h), pa1 = h2_as_u32(e2h, e3h);
            uint32_t pa2 = h2_as_u32(f0h, f1h), pa3 = h2_as_u32(f2h, f3h);
            uint32_t qa0 = h2_as_u32(
                __float2half_rn(sacc[2*kf][0] - __half2float(e0h)),
                __float2half_rn(sacc[2*kf][1] - __half2float(e1h)));
            uint32_t qa1 = h2_as_u32(
                __float2half_rn(sacc[2*kf][2] - __half2float(e2h)),
                __float2half_rn(sacc[2*kf][3] - __half2float(e3h)));
            uint32_t qa2 = h2_as_u32(
                __float2half_rn(sacc[2*kf+1][0] - __half2float(f0h)),
                __float2half_rn(sacc[2*kf+1][1] - __half2float(f1h)));
            uint32_t qa3 = h2_as_u32(
                __float2half_rn(sacc[2*kf+1][2] - __half2float(f2h)),
                __float2half_rn(sacc[2*kf+1][3] - __half2float(f3h)));

            uint32_t tadr = stbase + toff0 + kf * (16 * ATT_STR);
#pragma unroll
            for (int np2 = 0; np2 < 8; np2++) {
                uint32_t bh[4];
                LDSM_X4_T(bh[0], bh[1], bh[2], bh[3], tadr + ST_V + np2 * 32);
                MMA_F16(oacc[2*np2],   pa0, pa1, pa2, pa3, bh[0], bh[1]);
                MMA_F16(oacc[2*np2],   qa0, qa1, qa2, qa3, bh[0], bh[1]);
                MMA_F16(oacc[2*np2+1], pa0, pa1, pa2, pa3, bh[2], bh[3]);
                MMA_F16(oacc[2*np2+1], qa0, qa1, qa2, qa3, bh[2], bh[3]);
            }
        }
        __syncthreads();
    }

    // ---- normalize + write fp16 hi/lo
    float inv0 = 1.0f / l0, inv1 = 1.0f / l1;
    size_t r0 = (size_t)(b * SS + qb * 128 + wm + gid);
#pragma unroll
    for (int nf = 0; nf < 16; nf++) {
        int col = h * HD + nf * 8 + 2 * tig;
        float a0 = oacc[nf][0] * inv0, a1 = oacc[nf][1] * inv0;
        float a2 = oacc[nf][2] * inv1, a3 = oacc[nf][3] * inv1;
        __half h0 = __float2half_rn(a0), h1 = __float2half_rn(a1);
        __half h2v = __float2half_rn(a2), h3 = __float2half_rn(a3);
        *reinterpret_cast<uint32_t*>(&oh[r0 * HH + col]) = h2_as_u32(h0, h1);
        *reinterpret_cast<uint32_t*>(&oh[(r0 + 8) * HH + col]) = h2_as_u32(h2v, h3);
        *reinterpret_cast<uint32_t*>(&ol[r0 * HH + col]) =
            h2_as_u32(__float2half_rn(a0 - __half2float(h0)),
                      __float2half_rn(a1 - __half2float(h1)));
        *reinterpret_cast<uint32_t*>(&ol[(r0 + 8) * HH + col]) =
            h2_as_u32(__float2half_rn(a2 - __half2float(h2v)),
                      __float2half_rn(a3 - __half2float(h3)));
    }
}

// ---------------- launch ---------------------------------------------------
extern "C" void kernel_launch(void* const* d_in, const int* in_sizes, int n_in,
                              void* d_out, int out_size)
{
    const float* hidden = (const float*)d_in[0];
    const int*   mask   = (const int*)  d_in[1];
    const float* Wq = (const float*)d_in[2];
    const float* bq = (const float*)d_in[3];
    const float* Wk = (const float*)d_in[4];
    const float* bk = (const float*)d_in[5];
    const float* Wv = (const float*)d_in[6];
    const float* bv = (const float*)d_in[7];
    const float* Wo = (const float*)d_in[8];
    const float* bo = (const float*)d_in[9];
    float* out = (float*)d_out;

    __half *hh, *hl, *wq16, *wk16, *wv16, *wo16, *qh, *ql, *k, *v, *oh, *ol;
    float *maskb;
    cudaGetSymbolAddress((void**)&hh,    g_hh);
    cudaGetSymbolAddress((void**)&hl,    g_hl);
    cudaGetSymbolAddress((void**)&wq16,  g_wq16);
    cudaGetSymbolAddress((void**)&wk16,  g_wk16);
    cudaGetSymbolAddress((void**)&wv16,  g_wv16);
    cudaGetSymbolAddress((void**)&wo16,  g_wo16);
    cudaGetSymbolAddress((void**)&qh,    g_qh);
    cudaGetSymbolAddress((void**)&ql,    g_ql);
    cudaGetSymbolAddress((void**)&k,     g_k);
    cudaGetSymbolAddress((void**)&v,     g_v);
    cudaGetSymbolAddress((void**)&oh,    g_oh);
    cudaGetSymbolAddress((void**)&ol,    g_ol);
    cudaGetSymbolAddress((void**)&maskb, g_maskb);

    cudaFuncSetAttribute(gemm16,
        cudaFuncAttributeMaxDynamicSharedMemorySize, GSMEM);
    cudaFuncSetAttribute(flash_attn,
        cudaFuncAttributeMaxDynamicSharedMemorySize, ATT_SMEM);

    // one-shot conversions (off the MMA critical path)
    split_f32<<<(MM*HH/4 + 255)/256, 256>>>(hidden, hh, hl, MM*HH/4);
    to_f16<<<(HH*HH/4 + 255)/256, 256>>>(Wq, wq16, HH*HH/4);
    to_f16<<<(HD*HH/4 + 255)/256, 256>>>(Wk, wk16, HD*HH/4);
    to_f16<<<(HD*HH/4 + 255)/256, 256>>>(Wv, wv16, HD*HH/4);
    to_f16<<<(HH*HH/4 + 255)/256, 256>>>(Wo, wo16, HH*HH/4);
    prep_maskb<<<(BB*SS)/256, 256>>>(mask, maskb);

    // projections (pure-MMA pipelined)
    gemm16<<<dim3(16, 32), 256, GSMEM>>>(hh, hl, wq16, bq,
        nullptr, qh, ql, HH, HH, HH, HH, 1.f);
    gemm16<<<dim3(1, 32), 256, GSMEM>>>(hh, hl, wk16, bk,
        nullptr, k, nullptr, HH, HH, HH, HD, 1.f);
    gemm16<<<dim3(1, 32), 256, GSMEM>>>(hh, hl, wv16, bv,
        nullptr, v, nullptr, HH, HH, HH, HD, 1.f);

    // fused attention -> fp16 hi/lo
    flash_attn<<<dim3(SS/128, NH, BB), 256, ATT_SMEM>>>(
        qh, ql, k, v, maskb, oh, ol);

    // output projection -> fp32 d_out
    gemm16<<<dim3(16, 32), 256, GSMEM>>>(oh, ol, wo16, bo,
        out, nullptr, nullptr, HH, HH, HH, HH, 1.f);
}

// round 14
// speedup vs baseline: 1.1074x; 1.1074x over previous
#include <cuda_runtime.h>
#include <cuda_fp16.h>
#include <cstdint>
#include <cstring>

// Problem constants (fixed by the dataset)
#define BB 2
#define SS 2048
#define HH 2048
#define HD 128
#define NH 16
#define MM (BB*SS)   // 4096

// ---------------- scratch (static device globals — no allocation) ----------
__device__ __half g_q [(size_t)MM*HH];      // Q plain fp16 (B,S,H)
__device__ __half g_k [(size_t)MM*HD];      // K plain fp16 (B,S,hd)
__device__ __half g_v [(size_t)MM*HD];      // V plain fp16
__device__ float  g_attn[(size_t)MM*HH];    // attention output (B,S,H)
__device__ float  g_maskb[(size_t)BB*SS];   // mask bias: 0 or -1e30

// ---------------- helpers ---------------------------------------------------
__device__ __forceinline__ uint32_t smem_u32(const void* p) {
    uint32_t a;
    asm("{ .reg .u64 t; cvta.to.shared.u64 t, %1; cvt.u32.u64 %0, t; }"
        : "=r"(a) : "l"(p));
    return a;
}

#define MMA_F16(d, a0, a1, a2, a3, b0, b1) asm volatile( \
    "mma.sync.aligned.m16n8k16.row.col.f32.f16.f16.f32 " \
    "{%0,%1,%2,%3}, {%4,%5,%6,%7}, {%8,%9}, {%0,%1,%2,%3};" \
    : "+f"((d)[0]), "+f"((d)[1]), "+f"((d)[2]), "+f"((d)[3]) \
    : "r"(a0), "r"(a1), "r"(a2), "r"(a3), "r"(b0), "r"(b1))

#define LDSM_X4(r0, r1, r2, r3, addr) asm volatile( \
    "ldmatrix.sync.aligned.m8n8.x4.shared.b16 {%0,%1,%2,%3}, [%4];" \
    : "=r"(r0), "=r"(r1), "=r"(r2), "=r"(r3) : "r"(addr))

#define LDSM_X4_T(r0, r1, r2, r3, addr) asm volatile( \
    "ldmatrix.sync.aligned.m8n8.x4.trans.shared.b16 {%0,%1,%2,%3}, [%4];" \
    : "=r"(r0), "=r"(r1), "=r"(r2), "=r"(r3) : "r"(addr))

#define CP_ASYNC16(s, g) asm volatile( \
    "cp.async.ca.shared.global [%0], [%1], 16;" :: "r"(s), "l"(g))
#define CP_ASYNC4(s, g) asm volatile( \
    "cp.async.ca.shared.global [%0], [%1], 4;" :: "r"(s), "l"(g))
#define CP_COMMIT() asm volatile("cp.async.commit_group;")
#define CP_WAIT0() asm volatile("cp.async.wait_group 0;")
#define CP_WAIT1() asm volatile("cp.async.wait_group 1;")

__device__ __forceinline__ uint32_t h2_as_u32(__half x, __half y) {
    __half2 t = __halves2half2(x, y);
    uint32_t u; memcpy(&u, &t, 4); return u;
}

// ---------------- fp16x2 mma.sync NT GEMM (R9-measured skeleton) -----------
// C[m][n] = alpha * sum_k A[m][k]*B[n][k] (+ bias[n])
// A (activations) split hi/lo in smem; B (weights) plain fp16.
// Output: fp32 C, or plain fp16 (Ch).
#define RSTR 80
#define T_AH 0
#define T_AL 10240
#define T_BH 20480

__global__ __launch_bounds__(256)
void gemm_hmma(const float* __restrict__ A, const float* __restrict__ Bw,
               const float* __restrict__ bias, float* __restrict__ C,
               __half* __restrict__ Ch,
               int K, long long lda, long long ldb, long long ldc,
               float alpha)
{
    __shared__ __align__(16) unsigned char smem[30720];
    const uint32_t sb = smem_u32(smem);

    const int tid  = threadIdx.x;
    const int lane = tid & 31;
    const int warp = tid >> 5;
    const int gid  = lane >> 2;
    const int tig  = lane & 3;
    const int wm   = (warp >> 2) * 64;
    const int wn   = (warp & 3) * 32;

    const int rowBase = blockIdx.y * 128;
    const int colBase = blockIdx.x * 128;

    float acc[4][4][4];
#pragma unroll
    for (int i = 0; i < 4; i++)
#pragma unroll
        for (int j = 0; j < 4; j++)
#pragma unroll
            for (int c = 0; c < 4; c++) acc[i][j][c] = 0.f;

    const uint32_t aBase = sb + (uint32_t)((wm + (lane & 15)) * RSTR
                          + ((lane >> 4) & 1) * 16);
    const uint32_t bBase = sb + (uint32_t)((wn + ((lane >> 4) & 1) * 8
                          + (lane & 7)) * RSTR + ((lane >> 3) & 1) * 16);

    const int ldRow = tid >> 3;
    const int ldF4  = tid & 7;
    float4 pa[4], pb[4];
    auto loadChunk = [&](int c) {
        const int kt = c << 5;
#pragma unroll
        for (int i = 0; i < 4; i++) {
            int row = ldRow + i * 32;
            pa[i] = *reinterpret_cast<const float4*>(
                &A[(size_t)(rowBase + row) * lda + kt + ldF4 * 4]);
            pb[i] = *reinterpret_cast<const float4*>(
                &Bw[(size_t)(colBase + row) * ldb + kt + ldF4 * 4]);
        }
    };
    auto stsChunk = [&]() {
#pragma unroll
        for (int i = 0; i < 4; i++) {
            int row = ldRow + i * 32;
            uint32_t off = (uint32_t)(row * RSTR + ldF4 * 8);
            {
                float4 v = pa[i];
                __half hx = __float2half_rn(v.x), hy = __float2half_rn(v.y);
                __half hz = __float2half_rn(v.z), hw = __float2half_rn(v.w);
                *reinterpret_cast<uint2*>(smem + T_AH + off) =
                    make_uint2(h2_as_u32(hx, hy), h2_as_u32(hz, hw));
                *reinterpret_cast<uint2*>(smem + T_AL + off) = make_uint2(
                    h2_as_u32(__float2half_rn(v.x - __half2float(hx)),
                              __float2half_rn(v.y - __half2float(hy))),
                    h2_as_u32(__float2half_rn(v.z - __half2float(hz)),
                              __float2half_rn(v.w - __half2float(hw))));
            }
            {
                float4 v = pb[i];
                *reinterpret_cast<uint2*>(smem + T_BH + off) = make_uint2(
                    h2_as_u32(__float2half_rn(v.x), __float2half_rn(v.y)),
                    h2_as_u32(__float2half_rn(v.z), __float2half_rn(v.w)));
            }
        }
    };

    const int nchunks = K >> 5;
    loadChunk(0);
    for (int c = 0; c < nchunks; c++) {
        stsChunk();
        __syncthreads();
        if (c + 1 < nchunks) loadChunk(c + 1);

#pragma unroll
        for (int ks = 0; ks < 2; ks++) {
            const uint32_t ko = ks * 32;
            uint32_t ah[4][4], al[4][4], bh[4][2];
#pragma unroll
            for (int mf = 0; mf < 4; mf++) {
                uint32_t a = aBase + mf * (16 * RSTR) + ko;
                LDSM_X4(ah[mf][0], ah[mf][1], ah[mf][2], ah[mf][3], a + T_AH);
                LDSM_X4(al[mf][0], al[mf][1], al[mf][2], al[mf][3], a + T_AL);
            }
#pragma unroll
            for (int nfp = 0; nfp < 2; nfp++) {
                uint32_t b = bBase + nfp * (16 * RSTR) + ko;
                LDSM_X4(bh[2*nfp][0], bh[2*nfp][1], bh[2*nfp+1][0], bh[2*nfp+1][1],
                        b + T_BH);
            }
#pragma unroll
            for (int mf = 0; mf < 4; mf++)
#pragma unroll
                for (int nf = 0; nf < 4; nf++) {
                    MMA_F16(acc[mf][nf], ah[mf][0], ah[mf][1], ah[mf][2], ah[mf][3],
                            bh[nf][0], bh[nf][1]);
                    MMA_F16(acc[mf][nf], al[mf][0], al[mf][1], al[mf][2], al[mf][3],
                            bh[nf][0], bh[nf][1]);
                }
        }
        __syncthreads();
    }

#pragma unroll
    for (int mf = 0; mf < 4; mf++) {
        int r0 = rowBase + wm + mf * 16 + gid;
#pragma unroll
        for (int nf = 0; nf < 4; nf++) {
            int c0 = colBase + wn + nf * 8 + 2 * tig;
            float b0 = 0.f, b1 = 0.f;
            if (bias) { b0 = bias[c0]; b1 = bias[c0 + 1]; }
            float v00 = acc[mf][nf][0] * alpha + b0;
            float v01 = acc[mf][nf][1] * alpha + b1;
            float v10 = acc[mf][nf][2] * alpha + b0;
            float v11 = acc[mf][nf][3] * alpha + b1;
            if (Ch) {                // plain fp16 output (Q/K/V)
                *reinterpret_cast<uint32_t*>(&Ch[(size_t)r0 * ldc + c0]) =
                    h2_as_u32(__float2half_rn(v00), __float2half_rn(v01));
                *reinterpret_cast<uint32_t*>(&Ch[(size_t)(r0 + 8) * ldc + c0]) =
                    h2_as_u32(__float2half_rn(v10), __float2half_rn(v11));
            } else {                 // fp32 output
                *reinterpret_cast<float2*>(&C[(size_t)r0 * ldc + c0]) =
                    make_float2(v00, v01);
                *reinterpret_cast<float2*>(&C[(size_t)(r0 + 8) * ldc + c0]) =
                    make_float2(v10, v11);
            }
        }
    }
}

// ---------------- mask bias prep -------------------------------------------
__global__ void prep_maskb(const int* __restrict__ mask, float* __restrict__ mb)
{
    int i = blockIdx.x * 256 + threadIdx.x;
    if (i < BB * SS) mb[i] = mask[i] ? 0.f : -1e30f;
}

// ---------------- fused flash attention (plain fp16 MMAs) ------------------
// grid (S/128, NH, BB), 256 threads = 8 warps, each warp owns 16 q-rows.
// Q plain fp16 resident; K,V plain fp16 streamed 64-row double-buffered.
// Single MMA pass for QK^T and PV (precision budget spent here).
#define ATT_STR 272                      // 272 % 128 == 16 -> conflict-free
#define ATT_Q 0
#define ATT_STAGE0 (128*ATT_STR)         // 34816
#define ST_K 0
#define ST_V (64*ATT_STR)                // 17408
#define ST_MB (2*64*ATT_STR)             // 34816 (64 floats)
#define ATT_STAGE_SZ (2*64*ATT_STR + 256)   // 35072
#define ATT_SMEM (ATT_STAGE0 + 2*ATT_STAGE_SZ)  // 104960

__global__ __launch_bounds__(256)
void flash_attn(const __half* __restrict__ qq, const __half* __restrict__ kk,
                const __half* __restrict__ vv,
                const float* __restrict__ maskb, float* __restrict__ attn)
{
    extern __shared__ __align__(16) unsigned char sm[];
    const uint32_t sb = smem_u32(sm);
    const int tid  = threadIdx.x;
    const int lane = tid & 31;
    const int warp = tid >> 5;
    const int gid  = lane >> 2;
    const int tig  = lane & 3;
    const int qb = blockIdx.x, h = blockIdx.y, b = blockIdx.z;
    const int wm = warp * 16;

    // ---- Q tile async load: 128 rows x 256B
#pragma unroll
    for (int i = 0; i < 8; i++) {
        int row = (tid >> 4) + i * 16;         // 0..127
        int c16 = tid & 15;
        CP_ASYNC16(sb + ATT_Q + row * ATT_STR + c16 * 16,
                   qq + ((size_t)(b * SS + qb * 128 + row)) * HH + h * HD + c16 * 8);
    }
    CP_COMMIT();

    auto issue_kv = [&](int it, int stg) {
        uint32_t base = sb + ATT_STAGE0 + stg * ATT_STAGE_SZ;
        int kv0 = it * 64;
#pragma unroll
        for (int i = 0; i < 8; i++) {
            const __half* src = (i < 4) ? kk : vv;
            uint32_t aoff2 = (i < 4) ? ST_K : ST_V;
            int row = (tid >> 4) + (i & 3) * 16;
            int c16 = tid & 15;
            CP_ASYNC16(base + aoff2 + row * ATT_STR + c16 * 16,
                       src + ((size_t)(b * SS + kv0 + row)) * HD + c16 * 8);
        }
        if (tid < 64)
            CP_ASYNC4(base + ST_MB + tid * 4, maskb + b * SS + kv0 + tid);
        CP_COMMIT();
    };

    float oacc[16][4];
#pragma unroll
    for (int i = 0; i < 16; i++)
#pragma unroll
        for (int j = 0; j < 4; j++) oacc[i][j] = 0.f;
    float m0 = -1e30f, m1 = -1e30f, l0 = 0.f, l1 = 0.f;
    const float ascale = 0.08838834764831845f;

    issue_kv(0, 0);

    const uint32_t aoff = (uint32_t)((wm + (lane & 15)) * ATT_STR
                        + ((lane >> 4) & 1) * 16);
    const uint32_t boff = (uint32_t)((((lane >> 4) & 1) * 8 + (lane & 7)) * ATT_STR
                        + ((lane >> 3) & 1) * 16);
    const uint32_t toff0 = (uint32_t)((lane & 15) * ATT_STR
                         + ((lane >> 4) & 1) * 16);

    for (int it = 0; it < 32; it++) {
        const int stg = it & 1;
        if (it + 1 < 32) { issue_kv(it + 1, stg ^ 1); CP_WAIT1(); }
        else             { CP_WAIT0(); }
        __syncthreads();

        const uint32_t stbase = sb + ATT_STAGE0 + stg * ATT_STAGE_SZ;

        // ---- S = Q @ K^T (single fp16 pass)
        float sacc[8][4];
#pragma unroll
        for (int i = 0; i < 8; i++)
#pragma unroll
            for (int j = 0; j < 4; j++) sacc[i][j] = 0.f;

#pragma unroll
        for (int ks = 0; ks < 8; ks++) {
            const uint32_t ko = ks * 32;
            uint32_t ah[4];
            LDSM_X4(ah[0], ah[1], ah[2], ah[3], sb + ATT_Q + aoff + ko);
#pragma unroll
            for (int np = 0; np < 4; np++) {
                uint32_t bh[4];
                uint32_t ba = stbase + np * (16 * ATT_STR) + boff + ko;
                LDSM_X4(bh[0], bh[1], bh[2], bh[3], ba + ST_K);
                MMA_F16(sacc[2*np],   ah[0], ah[1], ah[2], ah[3], bh[0], bh[1]);
                MMA_F16(sacc[2*np+1], ah[0], ah[1], ah[2], ah[3], bh[2], bh[3]);
            }
        }

        // ---- scale + mask bias, online softmax (rows gid, gid+8)
        const float* mbp = reinterpret_cast<const float*>(
            sm + (size_t)(ATT_STAGE0 + stg * ATT_STAGE_SZ + ST_MB));
        float tm0 = -1e30f, tm1 = -1e30f;
#pragma unroll
        for (int nf = 0; nf < 8; nf++) {
            float mb0 = mbp[nf * 8 + 2 * tig];
            float mb1 = mbp[nf * 8 + 2 * tig + 1];
            sacc[nf][0] = sacc[nf][0] * ascale + mb0;
            sacc[nf][1] = sacc[nf][1] * ascale + mb1;
            sacc[nf][2] = sacc[nf][2] * ascale + mb0;
            sacc[nf][3] = sacc[nf][3] * ascale + mb1;
            tm0 = fmaxf(tm0, fmaxf(sacc[nf][0], sacc[nf][1]));
            tm1 = fmaxf(tm1, fmaxf(sacc[nf][2], sacc[nf][3]));
        }
        tm0 = fmaxf(tm0, __shfl_xor_sync(~0u, tm0, 1));
        tm0 = fmaxf(tm0, __shfl_xor_sync(~0u, tm0, 2));
        tm1 = fmaxf(tm1, __shfl_xor_sync(~0u, tm1, 1));
        tm1 = fmaxf(tm1, __shfl_xor_sync(~0u, tm1, 2));
        float nm0 = fmaxf(m0, tm0), nm1 = fmaxf(m1, tm1);
        float cor0 = __expf(m0 - nm0), cor1 = __expf(m1 - nm1);
        float rs0 = 0.f, rs1 = 0.f;
#pragma unroll
        for (int nf = 0; nf < 8; nf++) {
            sacc[nf][0] = __expf(sacc[nf][0] - nm0);
            sacc[nf][1] = __expf(sacc[nf][1] - nm0);
            sacc[nf][2] = __expf(sacc[nf][2] - nm1);
            sacc[nf][3] = __expf(sacc[nf][3] - nm1);
            rs0 += sacc[nf][0] + sacc[nf][1];
            rs1 += sacc[nf][2] + sacc[nf][3];
        }
        rs0 += __shfl_xor_sync(~0u, rs0, 1);
        rs0 += __shfl_xor_sync(~0u, rs0, 2);
        rs1 += __shfl_xor_sync(~0u, rs1, 1);
        rs1 += __shfl_xor_sync(~0u, rs1, 2);
        l0 = l0 * cor0 + rs0;  m0 = nm0;
        l1 = l1 * cor1 + rs1;  m1 = nm1;
#pragma unroll
        for (int nf = 0; nf < 16; nf++) {
            oacc[nf][0] *= cor0; oacc[nf][1] *= cor0;
            oacc[nf][2] *= cor1; oacc[nf][3] *= cor1;
        }

        // ---- out += P @ V (single fp16 pass; P packed from score accs)
#pragma unroll
        for (int kf = 0; kf < 4; kf++) {
            uint32_t pa0 = h2_as_u32(__float2half_rn(sacc[2*kf][0]),
                                     __float2half_rn(sacc[2*kf][1]));
            uint32_t pa1 = h2_as_u32(__float2half_rn(sacc[2*kf][2]),
                                     __float2half_rn(sacc[2*kf][3]));
            uint32_t pa2 = h2_as_u32(__float2half_rn(sacc[2*kf+1][0]),
                                     __float2half_rn(sacc[2*kf+1][1]));
            uint32_t pa3 = h2_as_u32(__float2half_rn(sacc[2*kf+1][2]),
                                     __float2half_rn(sacc[2*kf+1][3]));

            uint32_t tadr = stbase + toff0 + kf * (16 * ATT_STR);
#pragma unroll
            for (int np2 = 0; np2 < 8; np2++) {
                uint32_t bh[4];
                LDSM_X4_T(bh[0], bh[1], bh[2], bh[3], tadr + ST_V + np2 * 32);
                MMA_F16(oacc[2*np2],   pa0, pa1, pa2, pa3, bh[0], bh[1]);
                MMA_F16(oacc[2*np2+1], pa0, pa1, pa2, pa3, bh[2], bh[3]);
            }
        }
        __syncthreads();
    }

    // ---- normalize + write fp32 (B,S,H)
    float inv0 = 1.0f / l0, inv1 = 1.0f / l1;
    size_t r0 = (size_t)(b * SS + qb * 128 + wm + gid);
#pragma unroll
    for (int nf = 0; nf < 16; nf++) {
        int col = h * HD + nf * 8 + 2 * tig;
        *reinterpret_cast<float2*>(&attn[r0 * HH + col]) =
            make_float2(oacc[nf][0] * inv0, oacc[nf][1] * inv0);
        *reinterpret_cast<float2*>(&attn[(r0 + 8) * HH + col]) =
            make_float2(oacc[nf][2] * inv1, oacc[nf][3] * inv1);
    }
}

// ---------------- launch ---------------------------------------------------
extern "C" void kernel_launch(void* const* d_in, const int* in_sizes, int n_in,
                              void* d_out, int out_size)
{
    const float* hidden = (const float*)d_in[0];
    const int*   mask   = (const int*)  d_in[1];
    const float* Wq = (const float*)d_in[2];
    const float* bq = (const float*)d_in[3];
    const float* Wk = (const float*)d_in[4];
    const float* bk = (const float*)d_in[5];
    const float* Wv = (const float*)d_in[6];
    const float* bv = (const float*)d_in[7];
    const float* Wo = (const float*)d_in[8];
    const float* bo = (const float*)d_in[9];
    float* out = (float*)d_out;

    __half *q, *k, *v;
    float *attn, *maskb;
    cudaGetSymbolAddress((void**)&q,     g_q);
    cudaGetSymbolAddress((void**)&k,     g_k);
    cudaGetSymbolAddress((void**)&v,     g_v);
    cudaGetSymbolAddress((void**)&attn,  g_attn);
    cudaGetSymbolAddress((void**)&maskb, g_maskb);

    cudaFuncSetAttribute(flash_attn,
        cudaFuncAttributeMaxDynamicSharedMemorySize, ATT_SMEM);

    // projections (A split in-loop, weights plain fp16)
    gemm_hmma<<<dim3(16, 32), 256>>>(hidden, Wq, bq, nullptr, q,
                                     HH, HH, HH, HH, 1.f);
    gemm_hmma<<<dim3(1, 32), 256>>>(hidden, Wk, bk, nullptr, k,
                                    HH, HH, HH, HD, 1.f);
    gemm_hmma<<<dim3(1, 32), 256>>>(hidden, Wv, bv, nullptr, v,
                                    HH, HH, HH, HD, 1.f);
    prep_maskb<<<(BB*SS)/256, 256>>>(mask, maskb);
    // fused attention (single-pass fp16 MMAs)
    flash_attn<<<dim3(SS/128, NH, BB), 256, ATT_SMEM>>>(
        q, k, v, maskb, attn);
    // output projection -> fp32 d_out (A split in-loop)
    gemm_hmma<<<dim3(16, 32), 256>>>(attn, Wo, bo, out, nullptr,
                                     HH, HH, HH, HH, 1.f);
}